// round 7
// baseline (speedup 1.0000x reference)
#include <cuda_runtime.h>
#include <math.h>

#define NP   31752
#define D_   192
#define NA   256
#define LMB  0.1f
#define NSQ  11
#define T_   72
#define NTHR 288
#define NCTA 441

typedef unsigned long long ull;

// ---------------- static device scratch ----------------
__device__ float g_A[NA * D_];     // normalized dictionary [a][d]
__device__ float g_At[D_ * NA];    // transposed [d][a]
__device__ float g_X[NA * NA];
__device__ float g_Ma[NA * NA];
__device__ float g_Mb[NA * NA];
__device__ float g_fs[16];         // Frobenius^2 per stage
__device__ float g_params[4];      // L, 1/L, lambda/L
__device__ float g_mean[NP];
__device__ float g_rec[NP * D_];   // reconstruction [n][d]

__device__ __forceinline__ const float* pick(int id) {
    return id == 0 ? g_A : id == 1 ? g_X : id == 2 ? g_Ma : g_Mb;
}

// ---------------- f32x2 helpers ----------------
__device__ __forceinline__ ull pk2(float a, float b) {
    ull r; asm("mov.b64 %0, {%1,%2};" : "=l"(r) : "f"(a), "f"(b)); return r;
}
__device__ __forceinline__ ull f2fma(ull a, ull b, ull c) {
    ull d; asm("fma.rn.f32x2 %0, %1, %2, %3;" : "=l"(d) : "l"(a), "l"(b), "l"(c)); return d;
}
__device__ __forceinline__ void up2(ull v, float& lo, float& hi) {
    asm("mov.b64 {%0,%1}, %2;" : "=f"(lo), "=f"(hi) : "l"(v));
}

// ---------------- 1. normalize atoms (+ zero g_fs) ----------------
__global__ void k_norm(const float* __restrict__ atoms) {
    __shared__ float red[256];
    int r = blockIdx.x, t = threadIdx.x;
    if (r == 0 && t < 16) g_fs[t] = 0.f;
    float v = (t < D_) ? atoms[r * D_ + t] : 0.f;
    red[t] = v * v;
    __syncthreads();
    for (int o = 128; o > 0; o >>= 1) { if (t < o) red[t] += red[t + o]; __syncthreads(); }
    float inv = 1.0f / sqrtf(red[0]);
    if (t < D_) { float a = v * inv; g_A[r * D_ + t] = a; g_At[t * NA + r] = a; }
}

// ---------------- 2. Out = scale * In In^T, fused ||Out||_F^2 ----------------
// block (16,16), grid (8,8): 32x32 tile, 2x2 per thread
__global__ void k_mmT(int inId, int outId, int K, int fin, int fout) {
    __shared__ float As[32][17], Bs[32][17];
    const float* In = pick(inId);
    float* Out = (float*)pick(outId);
    int tx = threadIdx.x, ty = threadIdx.y;
    int tid = ty * 16 + tx;
    int row0 = blockIdx.y * 32, col0 = blockIdx.x * 32;
    float scale = (fin >= 0) ? 1.0f / g_fs[fin] : 1.0f;
    float acc[2][2] = {{0.f, 0.f}, {0.f, 0.f}};
    for (int kt = 0; kt < K; kt += 16) {
#pragma unroll
        for (int t = 0; t < 2; t++) {
            int i = tid + t * 256;
            int r = i >> 4, c = i & 15;
            As[r][c] = In[(row0 + r) * K + kt + c];
            Bs[r][c] = In[(col0 + r) * K + kt + c];
        }
        __syncthreads();
#pragma unroll
        for (int kk = 0; kk < 16; kk++) {
            float a0 = As[ty * 2][kk], a1 = As[ty * 2 + 1][kk];
            float b0 = Bs[tx * 2][kk], b1 = Bs[tx * 2 + 1][kk];
            acc[0][0] += a0 * b0; acc[0][1] += a0 * b1;
            acc[1][0] += a1 * b0; acc[1][1] += a1 * b1;
        }
        __syncthreads();
    }
    float fsum = 0.f;
#pragma unroll
    for (int i = 0; i < 2; i++)
#pragma unroll
        for (int j = 0; j < 2; j++) {
            float o = acc[i][j] * scale;
            Out[(row0 + ty * 2 + i) * NA + col0 + tx * 2 + j] = o;
            fsum += o * o;
        }
    if (fout >= 0) {
#pragma unroll
        for (int off = 16; off > 0; off >>= 1) fsum += __shfl_xor_sync(0xffffffffu, fsum, off);
        if ((tid & 31) == 0) atomicAdd(&g_fs[fout], fsum);
    }
}

// ---------------- 3. spectral norm assembly ----------------
__global__ void k_param(int srcId) {
    __shared__ float red[256];
    const float* M = pick(srcId);
    int t = threadIdx.x;
    red[t] = M[t * NA + t];
    __syncthreads();
    for (int o = 128; o > 0; o >>= 1) { if (t < o) red[t] += red[t + o]; __syncthreads(); }
    if (t == 0) {
        double lg = log((double)red[0]);
        for (int j = 1; j <= NSQ; j++)
            lg += (double)(1 << (NSQ - j)) * log((double)g_fs[j]);
        double L = exp(lg / (double)(1 << NSQ));
        g_params[0] = (float)L;
        g_params[1] = (float)(1.0 / L);
        g_params[2] = (float)((double)LMB / L);
    }
}

// ---------------- 4. per-patch mean ----------------
__global__ void k_mean(const float* __restrict__ y) {
    int n = blockIdx.x * 8 + (threadIdx.x >> 5);
    int l = threadIdx.x & 31;
    int b = n / 3969, r = n % 3969, i = r / 63, j = r % 63;
    float s = 0.f;
    for (int d = l; d < D_; d += 32) {
        int ch = d >> 6, u = (d >> 3) & 7, v = d & 7;
        s += y[((b * 3 + ch) * 256 + i * 4 + u) * 256 + j * 4 + v];
    }
    for (int o = 16; o > 0; o >>= 1) s += __shfl_xor_sync(0xffffffffu, s, o);
    if (l == 0) g_mean[n] = s * (1.f / 192.f);
}

// ---------------- fused q + ISTA + rec ----------------
// SMEM floats: cs[256*T_] | qs[256*T_] | Xs[2*16*256] | msh[T_]
#define CS_OFF 0
#define QS_OFF (256 * T_)
#define XS_OFF (2 * 256 * T_)
#define MS_OFF (XS_OFF + 8192)
#define SM_FLOATS (MS_OFF + T_)

// acc[RPT/2 row-pairs][8 cols] += M @ csrc ; M slab-streamed from gsrc
// gsrc: nslab slabs of [16][ROWLEN] floats; csrc: [16*nslab][T_]
template <int RPT, int ROWLEN>
__device__ __forceinline__ void slab_gemm(ull (&acc)[RPT / 2][8],
                                          const float* __restrict__ gsrc,
                                          const float* csrc, float* Xs,
                                          int nslab, int r0, int j0, int tid) {
    constexpr int CNT = 16 * ROWLEN;          // floats per slab
    constexpr int CNT4 = CNT / 4;             // float4 per slab
    constexpr int NPF = (CNT4 + NTHR - 1) / NTHR;
    // preload slab 0
#pragma unroll
    for (int t = 0; t < NPF; t++) {
        int i4 = tid + t * NTHR;
        if (i4 < CNT4)
            *(float4*)&Xs[i4 * 4] = *(const float4*)&gsrc[i4 * 4];
    }
    __syncthreads();
    for (int s = 0; s < nslab; s++) {
        float4 pf[NPF];
        if (s + 1 < nslab) {
            const float* src = gsrc + (s + 1) * CNT;
#pragma unroll
            for (int t = 0; t < NPF; t++) {
                int i4 = tid + t * NTHR;
                if (i4 < CNT4) pf[t] = *(const float4*)&src[i4 * 4];
            }
        }
        const float* Xb = Xs + (s & 1) * CNT;
        const float* cb = csrc + s * 16 * T_;
#pragma unroll
        for (int kk = 0; kk < 16; kk++) {
            const ull* Xr = (const ull*)(Xb + kk * ROWLEN + r0);
            float4 ca = *(const float4*)&cb[kk * T_ + j0];
            float4 cb4 = *(const float4*)&cb[kk * T_ + j0 + 4];
            ull cj[8];
            cj[0] = pk2(ca.x, ca.x);  cj[1] = pk2(ca.y, ca.y);
            cj[2] = pk2(ca.z, ca.z);  cj[3] = pk2(ca.w, ca.w);
            cj[4] = pk2(cb4.x, cb4.x); cj[5] = pk2(cb4.y, cb4.y);
            cj[6] = pk2(cb4.z, cb4.z); cj[7] = pk2(cb4.w, cb4.w);
#pragma unroll
            for (int rp = 0; rp < RPT / 2; rp++) {
                ull xp = Xr[rp];
#pragma unroll
                for (int j = 0; j < 8; j++)
                    acc[rp][j] = f2fma(xp, cj[j], acc[rp][j]);
            }
        }
        __syncthreads();
        if (s + 1 < nslab) {
            float* dst = Xs + ((s + 1) & 1) * CNT;
#pragma unroll
            for (int t = 0; t < NPF; t++) {
                int i4 = tid + t * NTHR;
                if (i4 < CNT4) *(float4*)&dst[i4 * 4] = pf[t];
            }
            __syncthreads();
        }
    }
}

__device__ __forceinline__ float softthr(float v, float thr) {
    float a = fabsf(v) - thr;
    return a > 0.f ? copysignf(a, v) : 0.f;
}

__global__ void __launch_bounds__(NTHR, 1) k_fused(const float* __restrict__ y) {
    extern __shared__ float sm[];
    float* cs = sm + CS_OFF;
    float* qs = sm + QS_OFF;
    float* Xs = sm + XS_OFF;
    float* msh = sm + MS_OFF;
    const int tid = threadIdx.x;
    const int n0 = blockIdx.x * T_;
    const int cg = tid % 9, rg = tid / 9;      // 9 col-groups x 32 row-groups
    const int j0 = cg * 8, r0 = rg * 8;
    const float invL = g_params[1], thr = g_params[2];

    // inline patch gather: cs[d][j] = y[patch n0+j, dim d] - mean
    for (int i = tid; i < D_ * T_; i += NTHR) {
        int j = i % T_, d = i / T_;
        int n = n0 + j;
        int b = n / 3969, r = n % 3969, ii = r / 63, jj = r % 63;
        int ch = d >> 6, u = (d >> 3) & 7, v = d & 7;
        cs[d * T_ + j] = y[((b * 3 + ch) * 256 + ii * 4 + u) * 256 + jj * 4 + v] - g_mean[n];
    }
    if (tid < T_) msh[tid] = g_mean[n0 + tid];
    // slab_gemm's first barrier orders these writes before reads

    ull acc[4][8];
#pragma unroll
    for (int a = 0; a < 4; a++)
#pragma unroll
        for (int b = 0; b < 8; b++) acc[a][b] = 0ull;

    // ---- prologue: q = A @ p^T  (contraction over d; gsrc = At[d][a]) ----
    slab_gemm<8, 256>(acc, g_At, cs, Xs, 12, r0, j0, tid);

    // store q; first ISTA step c = soft(q/L) overwrites cs
#pragma unroll
    for (int rp = 0; rp < 4; rp++) {
        int ra = r0 + 2 * rp, rb = ra + 1;
#pragma unroll
        for (int j = 0; j < 8; j++) {
            float lo, hi; up2(acc[rp][j], lo, hi);
            qs[ra * T_ + j0 + j] = lo;
            qs[rb * T_ + j0 + j] = hi;
            cs[ra * T_ + j0 + j] = softthr(lo * invL, thr);
            cs[rb * T_ + j0 + j] = softthr(hi * invL, thr);
        }
    }
    // next slab_gemm's preload barrier orders cs/qs writes before reads

    // ---- 24 remaining ISTA iterations ----
    for (int it = 0; it < 24; it++) {
#pragma unroll
        for (int a = 0; a < 4; a++)
#pragma unroll
            for (int b = 0; b < 8; b++) acc[a][b] = 0ull;
        slab_gemm<8, 256>(acc, g_X, cs, Xs, 16, r0, j0, tid);
#pragma unroll
        for (int rp = 0; rp < 4; rp++) {
            int ra = r0 + 2 * rp, rb = ra + 1;
            float4 qa0 = *(const float4*)&qs[ra * T_ + j0];
            float4 qa1 = *(const float4*)&qs[ra * T_ + j0 + 4];
            float4 qb0 = *(const float4*)&qs[rb * T_ + j0];
            float4 qb1 = *(const float4*)&qs[rb * T_ + j0 + 4];
            float4 ca0 = *(const float4*)&cs[ra * T_ + j0];
            float4 ca1 = *(const float4*)&cs[ra * T_ + j0 + 4];
            float4 cb0 = *(const float4*)&cs[rb * T_ + j0];
            float4 cb1 = *(const float4*)&cs[rb * T_ + j0 + 4];
            float qa[8] = {qa0.x, qa0.y, qa0.z, qa0.w, qa1.x, qa1.y, qa1.z, qa1.w};
            float qb[8] = {qb0.x, qb0.y, qb0.z, qb0.w, qb1.x, qb1.y, qb1.z, qb1.w};
            float cav[8] = {ca0.x, ca0.y, ca0.z, ca0.w, ca1.x, ca1.y, ca1.z, ca1.w};
            float cbv[8] = {cb0.x, cb0.y, cb0.z, cb0.w, cb1.x, cb1.y, cb1.z, cb1.w};
            float na_[8], nb_[8];
#pragma unroll
            for (int j = 0; j < 8; j++) {
                float lo, hi; up2(acc[rp][j], lo, hi);
                na_[j] = softthr(cav[j] - (lo - qa[j]) * invL, thr);
                nb_[j] = softthr(cbv[j] - (hi - qb[j]) * invL, thr);
            }
            *(float4*)&cs[ra * T_ + j0]     = make_float4(na_[0], na_[1], na_[2], na_[3]);
            *(float4*)&cs[ra * T_ + j0 + 4] = make_float4(na_[4], na_[5], na_[6], na_[7]);
            *(float4*)&cs[rb * T_ + j0]     = make_float4(nb_[0], nb_[1], nb_[2], nb_[3]);
            *(float4*)&cs[rb * T_ + j0 + 4] = make_float4(nb_[4], nb_[5], nb_[6], nb_[7]);
        }
    }

    // ---- epilogue: rec = c^T A + mean (contraction over atoms; gsrc = A[a][d]) ----
    {
        const int r0e = rg * 6;  // 32 groups x 6 d-rows = 192
        ull racc[3][8];
#pragma unroll
        for (int a = 0; a < 3; a++)
#pragma unroll
            for (int b = 0; b < 8; b++) racc[a][b] = 0ull;
        slab_gemm<6, 192>(racc, g_A, cs, Xs, 16, r0e, j0, tid);
#pragma unroll
        for (int j = 0; j < 8; j++) {
            int n = n0 + j0 + j;
            float m = msh[j0 + j];
            float* o = g_rec + (size_t)n * D_ + r0e;
#pragma unroll
            for (int rp = 0; rp < 3; rp++) {
                float lo, hi; up2(racc[rp][j], lo, hi);
                o[2 * rp] = lo + m;
                o[2 * rp + 1] = hi + m;
            }
        }
    }
}

// ---------------- overlap-add + count division ----------------
__global__ void k_out(float* __restrict__ out) {
    int idx = blockIdx.x * 256 + threadIdx.x;
    if (idx >= 8 * 3 * 256 * 256) return;
    int w = idx & 255, h = (idx >> 8) & 255;
    int ch = (idx >> 16) % 3, b = (idx >> 16) / 3;
    int ihi = h >> 2; if (ihi > 62) ihi = 62;
    int ilo = (h >= 7) ? ((h - 4) >> 2) : 0;
    int jhi = w >> 2; if (jhi > 62) jhi = 62;
    int jlo = (w >= 7) ? ((w - 4) >> 2) : 0;
    float s = 0.f;
    int cnt = 0;
    for (int i = ilo; i <= ihi; i++) {
        int u = h - 4 * i;
        for (int j = jlo; j <= jhi; j++) {
            int v = w - 4 * j;
            int n = b * 3969 + i * 63 + j;
            s += g_rec[(size_t)n * D_ + ch * 64 + u * 8 + v];
            cnt++;
        }
    }
    out[idx] = s / (float)cnt;
}

// ---------------- host launcher ----------------
extern "C" void kernel_launch(void* const* d_in, const int* in_sizes, int n_in,
                              void* d_out, int out_size) {
    const float* y = (const float*)d_in[0];
    const float* atoms = (const float*)d_in[1];
    if (n_in >= 2 && in_sizes[0] < in_sizes[1]) {
        y = (const float*)d_in[1];
        atoms = (const float*)d_in[0];
    }
    float* out = (float*)d_out;

    k_norm<<<NA, 256>>>(atoms);
    k_mmT<<<dim3(8, 8), dim3(16, 16)>>>(0, 1, D_, -1, 1);  // X = A A^T -> fs[1]
    int src = 1;
    for (int j = 1; j <= NSQ; j++) {
        int dst = (j & 1) ? 2 : 3;
        k_mmT<<<dim3(8, 8), dim3(16, 16)>>>(src, dst, NA, j, j + 1);
        src = dst;
    }
    k_param<<<1, 256>>>(src);
    k_mean<<<NP / 8, 256>>>(y);

    cudaFuncSetAttribute(k_fused, cudaFuncAttributeMaxDynamicSharedMemorySize,
                         SM_FLOATS * (int)sizeof(float));
    k_fused<<<NCTA, NTHR, SM_FLOATS * sizeof(float)>>>(y);

    k_out<<<(8 * 3 * 256 * 256 + 255) / 256, 256>>>(out);
}

// round 9
// speedup vs baseline: 1.3305x; 1.3305x over previous
#include <cuda_runtime.h>
#include <math.h>

#define NP   31752
#define D_   192
#define NA   256
#define LMB  0.1f
#define NSQ  10
#define T_   72
#define NTHR 576
#define NCTA 441
#define NB   64        // CTAs in k_chain (all co-resident)

typedef unsigned long long ull;

// ---------------- static device scratch ----------------
__device__ float g_A[NA * D_];     // normalized dictionary [a][d]
__device__ float g_At[D_ * NA];    // transposed [d][a]
__device__ float g_X[NA * NA];
__device__ float g_Ma[NA * NA];
__device__ float g_Mb[NA * NA];
__device__ float g_fs[16];         // Frobenius^2 per stage
__device__ float g_params[4];      // L, 1/L, lambda/L
__device__ float g_mean[NP];
__device__ float g_rec[NP * D_];   // reconstruction [n][d]
__device__ unsigned g_arrive = 0;  // grid-barrier counter (reset by k_reset)

// ---------------- f32x2 helpers ----------------
__device__ __forceinline__ ull pk2(float a, float b) {
    ull r; asm("mov.b64 %0, {%1,%2};" : "=l"(r) : "f"(a), "f"(b)); return r;
}
__device__ __forceinline__ ull f2fma(ull a, ull b, ull c) {
    ull d; asm("fma.rn.f32x2 %0, %1, %2, %3;" : "=l"(d) : "l"(a), "l"(b), "l"(c)); return d;
}
__device__ __forceinline__ void up2(ull v, float& lo, float& hi) {
    asm("mov.b64 {%0,%1}, %2;" : "=f"(lo), "=f"(hi) : "l"(v));
}

// ---------------- barrier-counter reset (runs before k_chain) ----------------
__global__ void k_reset() {
    if (threadIdx.x == 0) g_arrive = 0;
}

// ---------------- software grid barrier (64 co-resident CTAs) ----------------
__device__ __forceinline__ void gsync(unsigned target) {
    __threadfence();           // release: make prior writes visible
    __syncthreads();
    if (threadIdx.x == 0) {
        atomicAdd(&g_arrive, 1u);
        while (*((volatile unsigned*)&g_arrive) < target) { }
        __threadfence();       // gpu-scope fence -> CCTL.IVALL (L1 invalidate)
    }
    __syncthreads();
}

// ---------------- fused dictionary prep + Gram + spectral norm ----------------
// 64 CTAs x 256 threads. Each CTA owns 4 atom rows. Phases separated by gsync.
__global__ void __launch_bounds__(256, 1) k_chain(const float* __restrict__ atoms) {
    __shared__ float AshT[NA * 4];   // [k][r] transposed row block
    __shared__ float red[256];
    const int tid = threadIdx.x;
    const int cta = blockIdx.x;
    const int r0 = cta * 4;
    unsigned bar = 0;

    // ---- phase A: normalize rows r0..r0+3; zero g_fs ----
    if (cta == 0 && tid < 16) g_fs[tid] = 0.f;
    {
        int r = tid >> 6, l = tid & 63;     // 4 rows x 64 lanes
        int row = r0 + r;
        float v0 = atoms[row * D_ + l];
        float v1 = atoms[row * D_ + l + 64];
        float v2 = atoms[row * D_ + l + 128];
        red[tid] = v0 * v0 + v1 * v1 + v2 * v2;
        __syncthreads();
        for (int o = 32; o > 0; o >>= 1) {
            if (l < o) red[tid] += red[tid + o];
            __syncthreads();
        }
        float inv = 1.0f / sqrtf(red[r * 64]);
        float a0 = v0 * inv, a1 = v1 * inv, a2 = v2 * inv;
        g_A[row * D_ + l]        = a0;  g_At[l * NA + row]         = a0;
        g_A[row * D_ + l + 64]   = a1;  g_At[(l + 64) * NA + row]  = a1;
        g_A[row * D_ + l + 128]  = a2;  g_At[(l + 128) * NA + row] = a2;
    }
    gsync(++bar * NB);

    // ---- phase B: X = A A^T (rows r0..r0+3), fs[1] = ||X||_F^2 ----
    {
        for (int i = tid; i < 4 * D_; i += 256) {
            int r = i / D_, k = i % D_;
            AshT[k * 4 + r] = g_A[(r0 + r) * D_ + k];   // own rows
        }
        __syncthreads();
        int c = tid;
        float acc0 = 0.f, acc1 = 0.f, acc2 = 0.f, acc3 = 0.f;
        for (int k = 0; k < D_; k++) {
            float b = __ldcg(&g_At[k * NA + c]);
            float4 a4 = *(const float4*)&AshT[k * 4];
            acc0 += a4.x * b; acc1 += a4.y * b; acc2 += a4.z * b; acc3 += a4.w * b;
        }
        g_X[(r0 + 0) * NA + c] = acc0;
        g_X[(r0 + 1) * NA + c] = acc1;
        g_X[(r0 + 2) * NA + c] = acc2;
        g_X[(r0 + 3) * NA + c] = acc3;
        float fsum = acc0 * acc0 + acc1 * acc1 + acc2 * acc2 + acc3 * acc3;
#pragma unroll
        for (int o = 16; o > 0; o >>= 1) fsum += __shfl_xor_sync(0xffffffffu, fsum, o);
        if ((tid & 31) == 0) atomicAdd(&g_fs[1], fsum);
        __syncthreads();   // AshT reuse safety
    }
    gsync(++bar * NB);

    // ---- phase C: NSQ scaled squarings M_{j+1} = M_j^2 / ||M_j||_F^2 ----
    const float* In = g_X;
    float* Out = g_Ma;
    for (int j = 1; j <= NSQ; j++) {
        float scale = 1.0f / __ldcg(&g_fs[j]);
        for (int i = tid; i < 1024; i += 256) {
            int r = i >> 8, k = i & 255;
            AshT[k * 4 + r] = __ldcg(&In[(r0 + r) * NA + k]);   // own rows
        }
        __syncthreads();
        int c = tid;
        float acc0 = 0.f, acc1 = 0.f, acc2 = 0.f, acc3 = 0.f;
        for (int k = 0; k < NA; k++) {
            float b = __ldcg(&In[k * NA + c]);   // symmetric: column c = row c
            float4 a4 = *(const float4*)&AshT[k * 4];
            acc0 += a4.x * b; acc1 += a4.y * b; acc2 += a4.z * b; acc3 += a4.w * b;
        }
        acc0 *= scale; acc1 *= scale; acc2 *= scale; acc3 *= scale;
        Out[(r0 + 0) * NA + c] = acc0;
        Out[(r0 + 1) * NA + c] = acc1;
        Out[(r0 + 2) * NA + c] = acc2;
        Out[(r0 + 3) * NA + c] = acc3;
        float fsum = acc0 * acc0 + acc1 * acc1 + acc2 * acc2 + acc3 * acc3;
#pragma unroll
        for (int o = 16; o > 0; o >>= 1) fsum += __shfl_xor_sync(0xffffffffu, fsum, o);
        if ((tid & 31) == 0) atomicAdd(&g_fs[j + 1], fsum);
        const float* nIn = Out;
        Out = (Out == g_Ma) ? g_Mb : g_Ma;
        In = nIn;
        gsync(++bar * NB);
    }

    // ---- phase D: trace of final matrix -> L, params (CTA0 only) ----
    if (cta == 0) {
        red[tid] = __ldcg(&In[tid * NA + tid]);
        __syncthreads();
        for (int o = 128; o > 0; o >>= 1) {
            if (tid < o) red[tid] += red[tid + o];
            __syncthreads();
        }
        if (tid == 0) {
            double lg = log((double)red[0]);
            for (int j = 1; j <= NSQ; j++)
                lg += (double)(1 << (NSQ - j)) * log((double)__ldcg(&g_fs[j]));
            double L = exp(lg / (double)(1 << NSQ));
            g_params[0] = (float)L;
            g_params[1] = (float)(1.0 / L);
            g_params[2] = (float)((double)LMB / L);
        }
    }
}

// ---------------- per-patch mean (split into 3 launches) ----------------
__global__ void k_mean(const float* __restrict__ y, int blockOff) {
    int n = (blockOff + blockIdx.x) * 8 + (threadIdx.x >> 5);
    int l = threadIdx.x & 31;
    int b = n / 3969, r = n % 3969, i = r / 63, j = r % 63;
    float s = 0.f;
    for (int d = l; d < D_; d += 32) {
        int ch = d >> 6, u = (d >> 3) & 7, v = d & 7;
        s += y[((b * 3 + ch) * 256 + i * 4 + u) * 256 + j * 4 + v];
    }
    for (int o = 16; o > 0; o >>= 1) s += __shfl_xor_sync(0xffffffffu, s, o);
    if (l == 0) g_mean[n] = s * (1.f / 192.f);
}

// ---------------- fused q + ISTA + rec (R3-proven hot loop) ----------------
// SMEM floats: cs[256*72] | qs[256*72] | Xsh[2*16*256] | mean[72]
#define CS_OFF 0
#define QS_OFF (256 * T_)
#define XS_OFF (2 * 256 * T_)
#define MS_OFF (XS_OFF + 2 * 16 * 256)
#define SM_FLOATS (MS_OFF + T_)

// acc rows r0..r0+7 (4 f32x2 pairs) x cols j0..j0+3; gsrc: nslab 16x256 slabs
__device__ __forceinline__ void slab_gemm(ull acc[4][4], const float* __restrict__ gsrc,
                                          const float* csrc, float* Xsh,
                                          int nslab, int r0, int j0, int tid) {
    for (int i = tid; i < 1024; i += NTHR) {
        int kk = i >> 6, r4 = (i & 63) << 2;
        *(float4*)&Xsh[kk * 256 + r4] = *(const float4*)&gsrc[kk * 256 + r4];
    }
    __syncthreads();
    for (int s = 0; s < nslab; s++) {
        float4 pf0, pf1;
        bool have1 = false;
        if (s + 1 < nslab) {
            const float* src = gsrc + (s + 1) * 4096;
            int kk = tid >> 6, r4 = (tid & 63) << 2;
            pf0 = *(const float4*)&src[kk * 256 + r4];
            if (tid + NTHR < 1024) {
                int i1 = tid + NTHR; kk = i1 >> 6; r4 = (i1 & 63) << 2;
                pf1 = *(const float4*)&src[kk * 256 + r4];
                have1 = true;
            }
        }
        const float* Xb = Xsh + (s & 1) * 4096;
        const float* cb = csrc + s * 16 * T_;
#pragma unroll
        for (int kk = 0; kk < 16; kk++) {
            ulonglong2 xa = *(const ulonglong2*)&Xb[kk * 256 + r0];
            ulonglong2 xb = *(const ulonglong2*)&Xb[kk * 256 + r0 + 4];
            float4 cv = *(const float4*)&cb[kk * T_ + j0];
            ull c0 = pk2(cv.x, cv.x), c1 = pk2(cv.y, cv.y);
            ull c2 = pk2(cv.z, cv.z), c3 = pk2(cv.w, cv.w);
            acc[0][0] = f2fma(xa.x, c0, acc[0][0]); acc[1][0] = f2fma(xa.y, c0, acc[1][0]);
            acc[2][0] = f2fma(xb.x, c0, acc[2][0]); acc[3][0] = f2fma(xb.y, c0, acc[3][0]);
            acc[0][1] = f2fma(xa.x, c1, acc[0][1]); acc[1][1] = f2fma(xa.y, c1, acc[1][1]);
            acc[2][1] = f2fma(xb.x, c1, acc[2][1]); acc[3][1] = f2fma(xb.y, c1, acc[3][1]);
            acc[0][2] = f2fma(xa.x, c2, acc[0][2]); acc[1][2] = f2fma(xa.y, c2, acc[1][2]);
            acc[2][2] = f2fma(xb.x, c2, acc[2][2]); acc[3][2] = f2fma(xb.y, c2, acc[3][2]);
            acc[0][3] = f2fma(xa.x, c3, acc[0][3]); acc[1][3] = f2fma(xa.y, c3, acc[1][3]);
            acc[2][3] = f2fma(xb.x, c3, acc[2][3]); acc[3][3] = f2fma(xb.y, c3, acc[3][3]);
        }
        __syncthreads();
        if (s + 1 < nslab) {
            float* dst = Xsh + ((s + 1) & 1) * 4096;
            int kk = tid >> 6, r4 = (tid & 63) << 2;
            *(float4*)&dst[kk * 256 + r4] = pf0;
            if (have1) {
                int i1 = tid + NTHR; kk = i1 >> 6; r4 = (i1 & 63) << 2;
                *(float4*)&dst[kk * 256 + r4] = pf1;
            }
            __syncthreads();
        }
    }
}

__global__ void __launch_bounds__(NTHR, 1) k_fused(const float* __restrict__ y) {
    extern __shared__ float sm[];
    float* cs = sm + CS_OFF;
    float* qs = sm + QS_OFF;
    float* Xsh = sm + XS_OFF;
    float* msh = sm + MS_OFF;
    const int tid = threadIdx.x;
    const int n0 = blockIdx.x * T_;
    const int cg = tid % 18, rg = tid / 18;
    const int j0 = cg * 4, r0 = rg * 8;
    const float invL = g_params[1], thr = g_params[2];

    // inline centered-patch gather (d-major) + mean tile
    for (int i = tid; i < D_ * T_; i += NTHR) {
        int d = i / T_, jj = i % T_;
        int n = n0 + jj;
        int b = n / 3969, rr = n % 3969, pi = rr / 63, pj = rr % 63;
        int ch = d >> 6, u = (d >> 3) & 7, v = d & 7;
        cs[i] = y[((b * 3 + ch) * 256 + pi * 4 + u) * 256 + pj * 4 + v] - g_mean[n];
    }
    if (tid < T_) msh[tid] = g_mean[n0 + tid];
    __syncthreads();

    ull acc[4][4];
#pragma unroll
    for (int a = 0; a < 4; a++)
#pragma unroll
        for (int b = 0; b < 4; b++) acc[a][b] = 0ull;

    // ---- prologue: qs = A @ p^T  (K = 192: 12 slabs of g_At) ----
    slab_gemm(acc, g_At, cs, Xsh, 12, r0, j0, tid);
#pragma unroll
    for (int rp = 0; rp < 4; rp++)
#pragma unroll
        for (int jj = 0; jj < 4; jj++) {
            float lo, hi; up2(acc[rp][jj], lo, hi);
            qs[(r0 + 2 * rp) * T_ + j0 + jj] = lo;
            qs[(r0 + 2 * rp + 1) * T_ + j0 + jj] = hi;
        }
    __syncthreads();
    for (int i = tid; i < 256 * T_; i += NTHR) cs[i] = 0.f;
    __syncthreads();

    // ---- 25 ISTA iterations ----
    for (int it = 0; it < 25; it++) {
#pragma unroll
        for (int a = 0; a < 4; a++)
#pragma unroll
            for (int b = 0; b < 4; b++) acc[a][b] = 0ull;
        if (it > 0) slab_gemm(acc, g_X, cs, Xsh, 16, r0, j0, tid);
#pragma unroll
        for (int rp = 0; rp < 4; rp++)
#pragma unroll
            for (int jj = 0; jj < 4; jj++) {
                float lo, hi; up2(acc[rp][jj], lo, hi);
                int ra = r0 + 2 * rp, rb = ra + 1;
                float va = cs[ra * T_ + j0 + jj] - (lo - qs[ra * T_ + j0 + jj]) * invL;
                float vb = cs[rb * T_ + j0 + jj] - (hi - qs[rb * T_ + j0 + jj]) * invL;
                float aa = fabsf(va) - thr;
                float ab = fabsf(vb) - thr;
                cs[ra * T_ + j0 + jj] = aa > 0.f ? copysignf(aa, va) : 0.f;
                cs[rb * T_ + j0 + jj] = ab > 0.f ? copysignf(ab, vb) : 0.f;
            }
        __syncthreads();
    }

    // ---- epilogue: rec = c^T A + mean (K = 256 atoms: 16 slabs of g_A [16][192]) ----
    {
        const int dg = tid & 31, jg = tid >> 5;
        const int d0 = dg * 6, j0e = jg * 4;
        ull racc[4][3];
#pragma unroll
        for (int a = 0; a < 4; a++)
#pragma unroll
            for (int b = 0; b < 3; b++) racc[a][b] = 0ull;
        for (int i = tid; i < 768; i += NTHR) {
            int aa = i / 48, dd = (i % 48) * 4;
            *(float4*)&Xsh[aa * 192 + dd] = *(const float4*)&g_A[aa * 192 + dd];
        }
        __syncthreads();
        for (int s = 0; s < 16; s++) {
            float4 pf0, pf1;
            bool have1 = false;
            if (s + 1 < 16) {
                const float* src = g_A + (s + 1) * 3072;
                int aa = tid / 48, dd = (tid % 48) * 4;
                pf0 = *(const float4*)&src[aa * 192 + dd];
                if (tid + NTHR < 768) {
                    int i1 = tid + NTHR; aa = i1 / 48; dd = (i1 % 48) * 4;
                    pf1 = *(const float4*)&src[aa * 192 + dd];
                    have1 = true;
                }
            }
            const float* Ab = Xsh + (s & 1) * 3072;
#pragma unroll
            for (int kk = 0; kk < 16; kk++) {
                int a = s * 16 + kk;
                float4 cv = *(const float4*)&cs[a * T_ + j0e];
                ull ap0 = *(const ull*)&Ab[kk * 192 + d0];
                ull ap1 = *(const ull*)&Ab[kk * 192 + d0 + 2];
                ull ap2 = *(const ull*)&Ab[kk * 192 + d0 + 4];
                ull c0 = pk2(cv.x, cv.x), c1 = pk2(cv.y, cv.y);
                ull c2 = pk2(cv.z, cv.z), c3 = pk2(cv.w, cv.w);
                racc[0][0] = f2fma(ap0, c0, racc[0][0]); racc[0][1] = f2fma(ap1, c0, racc[0][1]); racc[0][2] = f2fma(ap2, c0, racc[0][2]);
                racc[1][0] = f2fma(ap0, c1, racc[1][0]); racc[1][1] = f2fma(ap1, c1, racc[1][1]); racc[1][2] = f2fma(ap2, c1, racc[1][2]);
                racc[2][0] = f2fma(ap0, c2, racc[2][0]); racc[2][1] = f2fma(ap1, c2, racc[2][1]); racc[2][2] = f2fma(ap2, c2, racc[2][2]);
                racc[3][0] = f2fma(ap0, c3, racc[3][0]); racc[3][1] = f2fma(ap1, c3, racc[3][1]); racc[3][2] = f2fma(ap2, c3, racc[3][2]);
            }
            __syncthreads();
            if (s + 1 < 16) {
                float* dst = Xsh + ((s + 1) & 1) * 3072;
                int aa = tid / 48, dd = (tid % 48) * 4;
                *(float4*)&dst[aa * 192 + dd] = pf0;
                if (have1) {
                    int i1 = tid + NTHR; aa = i1 / 48; dd = (i1 % 48) * 4;
                    *(float4*)&dst[aa * 192 + dd] = pf1;
                }
                __syncthreads();
            }
        }
#pragma unroll
        for (int jj = 0; jj < 4; jj++) {
            int n = n0 + j0e + jj;
            float m = msh[j0e + jj];
            float* o = g_rec + (size_t)n * D_ + d0;
#pragma unroll
            for (int dp = 0; dp < 3; dp++) {
                float lo, hi; up2(racc[jj][dp], lo, hi);
                o[2 * dp] = lo + m;
                o[2 * dp + 1] = hi + m;
            }
        }
    }
}

// ---------------- overlap-add + count division ----------------
__global__ void k_out(float* __restrict__ out) {
    int idx = blockIdx.x * 256 + threadIdx.x;
    if (idx >= 8 * 3 * 256 * 256) return;
    int w = idx & 255, h = (idx >> 8) & 255;
    int ch = (idx >> 16) % 3, b = (idx >> 16) / 3;
    int ihi = h >> 2; if (ihi > 62) ihi = 62;
    int ilo = (h >= 7) ? ((h - 4) >> 2) : 0;
    int jhi = w >> 2; if (jhi > 62) jhi = 62;
    int jlo = (w >= 7) ? ((w - 4) >> 2) : 0;
    float s = 0.f;
    int cnt = 0;
    for (int i = ilo; i <= ihi; i++) {
        int u = h - 4 * i;
        for (int j = jlo; j <= jhi; j++) {
            int v = w - 4 * j;
            int n = b * 3969 + i * 63 + j;
            s += g_rec[(size_t)n * D_ + ch * 64 + u * 8 + v];
            cnt++;
        }
    }
    out[idx] = s / (float)cnt;
}

// ---------------- host launcher ----------------
extern "C" void kernel_launch(void* const* d_in, const int* in_sizes, int n_in,
                              void* d_out, int out_size) {
    const float* y = (const float*)d_in[0];
    const float* atoms = (const float*)d_in[1];
    if (n_in >= 2 && in_sizes[0] < in_sizes[1]) {
        y = (const float*)d_in[1];
        atoms = (const float*)d_in[0];
    }
    float* out = (float*)d_out;

    k_reset<<<1, 32>>>();                 // launch 0
    k_chain<<<NB, 256>>>(atoms);          // launch 1: Gram + spectral norm + params
    k_mean<<<1323, 256>>>(y, 0);          // launches 2-4 (3969 blocks total)
    k_mean<<<1323, 256>>>(y, 1323);
    k_mean<<<1323, 256>>>(y, 2646);

    cudaFuncSetAttribute(k_fused, cudaFuncAttributeMaxDynamicSharedMemorySize,
                         SM_FLOATS * (int)sizeof(float));
    k_fused<<<NCTA, NTHR, SM_FLOATS * sizeof(float)>>>(y);   // launch 5 (profiled)

    k_out<<<(8 * 3 * 256 * 256 + 255) / 256, 256>>>(out);    // launch 6
}

// round 11
// speedup vs baseline: 3.4978x; 2.6289x over previous
#include <cuda_runtime.h>
#include <cuda_fp16.h>
#include <math.h>

#define NP   31752
#define D_   192
#define NA   256
#define LMB  0.1f
#define NSQ  10
#define T_   72
#define NCTA 441
#define NB   64
#define CSTR 264                 // padded cs row stride in halfs

typedef unsigned long long ull;
typedef unsigned int u32;

// ---------------- static device scratch ----------------
__device__ float  g_A[NA * D_];
__device__ float  g_At[D_ * NA];
__device__ float  g_X[NA * NA];
__device__ float  g_Ma[NA * NA];
__device__ float  g_Mb[NA * NA];
__device__ __half g_XfH[16 * 16 * 32 * 8];   // X fragments hi [s][t][lane][8]
__device__ __half g_XfL[16 * 16 * 32 * 8];
__device__ __half g_AfH[12 * 16 * 32 * 8];   // dict fragments hi
__device__ __half g_AfL[12 * 16 * 32 * 8];
__device__ float  g_fs[16];
__device__ float  g_params[4];
__device__ float  g_mean[NP];
__device__ float  g_c[(size_t)NP * NA];
__device__ float  g_rec[(size_t)NP * D_];
__device__ unsigned g_arrive = 0;

// ---------------- helpers ----------------
__device__ __forceinline__ ull pk2(float a, float b) {
    ull r; asm("mov.b64 %0, {%1,%2};" : "=l"(r) : "f"(a), "f"(b)); return r;
}
__device__ __forceinline__ ull f2fma(ull a, ull b, ull c) {
    ull d; asm("fma.rn.f32x2 %0, %1, %2, %3;" : "=l"(d) : "l"(a), "l"(b), "l"(c)); return d;
}
__device__ __forceinline__ void up2(ull v, float& lo, float& hi) {
    asm("mov.b64 {%0,%1}, %2;" : "=f"(lo), "=f"(hi) : "l"(v));
}
__device__ __forceinline__ float softthr(float v, float thr) {
    float a = fabsf(v) - thr;
    return a > 0.f ? copysignf(a, v) : 0.f;
}
__device__ __forceinline__ void mma16816(float* d, const u32* a, u32 b0, u32 b1) {
    asm volatile(
        "mma.sync.aligned.m16n8k16.row.col.f32.f16.f16.f32 "
        "{%0,%1,%2,%3}, {%4,%5,%6,%7}, {%8,%9}, {%0,%1,%2,%3};"
        : "+f"(d[0]), "+f"(d[1]), "+f"(d[2]), "+f"(d[3])
        : "r"(a[0]), "r"(a[1]), "r"(a[2]), "r"(a[3]), "r"(b0), "r"(b1));
}

// ---------------- k_reset + grid barrier ----------------
__global__ void k_reset() { if (threadIdx.x == 0) g_arrive = 0; }

__device__ __forceinline__ void gsync(unsigned target) {
    __threadfence();
    __syncthreads();
    if (threadIdx.x == 0) {
        atomicAdd(&g_arrive, 1u);
        while (*((volatile unsigned*)&g_arrive) < target) { }
        __threadfence();
    }
    __syncthreads();
}

// ---------------- k_chain (proven R7): normalize + Gram + spectral norm ----------------
__global__ void __launch_bounds__(256, 1) k_chain(const float* __restrict__ atoms) {
    __shared__ float AshT[NA * 4];
    __shared__ float red[256];
    const int tid = threadIdx.x;
    const int cta = blockIdx.x;
    const int r0 = cta * 4;
    unsigned bar = 0;

    if (cta == 0 && tid < 16) g_fs[tid] = 0.f;
    {
        int r = tid >> 6, l = tid & 63;
        int row = r0 + r;
        float v0 = atoms[row * D_ + l];
        float v1 = atoms[row * D_ + l + 64];
        float v2 = atoms[row * D_ + l + 128];
        red[tid] = v0 * v0 + v1 * v1 + v2 * v2;
        __syncthreads();
        for (int o = 32; o > 0; o >>= 1) {
            if (l < o) red[tid] += red[tid + o];
            __syncthreads();
        }
        float inv = 1.0f / sqrtf(red[r * 64]);
        float a0 = v0 * inv, a1 = v1 * inv, a2 = v2 * inv;
        g_A[row * D_ + l]       = a0;  g_At[l * NA + row]         = a0;
        g_A[row * D_ + l + 64]  = a1;  g_At[(l + 64) * NA + row]  = a1;
        g_A[row * D_ + l + 128] = a2;  g_At[(l + 128) * NA + row] = a2;
    }
    gsync(++bar * NB);

    {
        for (int i = tid; i < 4 * D_; i += 256) {
            int r = i / D_, k = i % D_;
            AshT[k * 4 + r] = g_A[(r0 + r) * D_ + k];
        }
        __syncthreads();
        int c = tid;
        float acc0 = 0.f, acc1 = 0.f, acc2 = 0.f, acc3 = 0.f;
        for (int k = 0; k < D_; k++) {
            float b = __ldcg(&g_At[k * NA + c]);
            float4 a4 = *(const float4*)&AshT[k * 4];
            acc0 += a4.x * b; acc1 += a4.y * b; acc2 += a4.z * b; acc3 += a4.w * b;
        }
        g_X[(r0 + 0) * NA + c] = acc0;
        g_X[(r0 + 1) * NA + c] = acc1;
        g_X[(r0 + 2) * NA + c] = acc2;
        g_X[(r0 + 3) * NA + c] = acc3;
        float fsum = acc0 * acc0 + acc1 * acc1 + acc2 * acc2 + acc3 * acc3;
#pragma unroll
        for (int o = 16; o > 0; o >>= 1) fsum += __shfl_xor_sync(0xffffffffu, fsum, o);
        if ((tid & 31) == 0) atomicAdd(&g_fs[1], fsum);
        __syncthreads();
    }
    gsync(++bar * NB);

    const float* In = g_X;
    float* Out = g_Ma;
    for (int j = 1; j <= NSQ; j++) {
        float scale = 1.0f / __ldcg(&g_fs[j]);
        for (int i = tid; i < 1024; i += 256) {
            int r = i >> 8, k = i & 255;
            AshT[k * 4 + r] = __ldcg(&In[(r0 + r) * NA + k]);
        }
        __syncthreads();
        int c = tid;
        float acc0 = 0.f, acc1 = 0.f, acc2 = 0.f, acc3 = 0.f;
        for (int k = 0; k < NA; k++) {
            float b = __ldcg(&In[k * NA + c]);
            float4 a4 = *(const float4*)&AshT[k * 4];
            acc0 += a4.x * b; acc1 += a4.y * b; acc2 += a4.z * b; acc3 += a4.w * b;
        }
        acc0 *= scale; acc1 *= scale; acc2 *= scale; acc3 *= scale;
        Out[(r0 + 0) * NA + c] = acc0;
        Out[(r0 + 1) * NA + c] = acc1;
        Out[(r0 + 2) * NA + c] = acc2;
        Out[(r0 + 3) * NA + c] = acc3;
        float fsum = acc0 * acc0 + acc1 * acc1 + acc2 * acc2 + acc3 * acc3;
#pragma unroll
        for (int o = 16; o > 0; o >>= 1) fsum += __shfl_xor_sync(0xffffffffu, fsum, o);
        if ((tid & 31) == 0) atomicAdd(&g_fs[j + 1], fsum);
        const float* nIn = Out;
        Out = (Out == g_Ma) ? g_Mb : g_Ma;
        In = nIn;
        gsync(++bar * NB);
    }

    if (cta == 0) {
        red[tid] = __ldcg(&In[tid * NA + tid]);
        __syncthreads();
        for (int o = 128; o > 0; o >>= 1) {
            if (tid < o) red[tid] += red[tid + o];
            __syncthreads();
        }
        if (tid == 0) {
            double lg = log((double)red[0]);
            for (int j = 1; j <= NSQ; j++)
                lg += (double)(1 << (NSQ - j)) * log((double)__ldcg(&g_fs[j]));
            double L = exp(lg / (double)(1 << NSQ));
            g_params[0] = (float)L;
            g_params[1] = (float)(1.0 / L);
            g_params[2] = (float)((double)LMB / L);
        }
    }
}

// ---------------- k_mean ----------------
__global__ void k_mean(const float* __restrict__ y) {
    int n = blockIdx.x * 8 + (threadIdx.x >> 5);
    int l = threadIdx.x & 31;
    int b = n / 3969, r = n % 3969, i = r / 63, j = r % 63;
    float s = 0.f;
    for (int d = l; d < D_; d += 32) {
        int ch = d >> 6, u = (d >> 3) & 7, v = d & 7;
        s += y[((b * 3 + ch) * 256 + i * 4 + u) * 256 + j * 4 + v];
    }
    for (int o = 16; o > 0; o >>= 1) s += __shfl_xor_sync(0xffffffffu, s, o);
    if (l == 0) g_mean[n] = s * (1.f / 192.f);
}

// ---------------- fragment pre-swizzle kernels ----------------
// layout: frag[((s*16 + t)*32 + lane)*8] = {M[r][k],M[r][k+1],M[r+8][k],M[r+8][k+1],
//                                           M[r][k+8],M[r][k+9],M[r+8][k+8],M[r+8][k+9]}
// with r = t*16 + g, k = s*16 + 2*tg
__device__ __forceinline__ void frag_write(__half* dH, __half* dL,
                                           const float* __restrict__ src, int stride,
                                           int id) {
    int lane = id & 31, t = (id >> 5) & 15, s = id >> 9;
    int g = lane >> 2, tg = lane & 3;
    int r = t * 16 + g, k = s * 16 + 2 * tg;
    float v[8];
    v[0] = src[r * stride + k];         v[1] = src[r * stride + k + 1];
    v[2] = src[(r + 8) * stride + k];   v[3] = src[(r + 8) * stride + k + 1];
    v[4] = src[r * stride + k + 8];     v[5] = src[r * stride + k + 9];
    v[6] = src[(r + 8) * stride + k + 8]; v[7] = src[(r + 8) * stride + k + 9];
    u32 ph[4], pl[4];
#pragma unroll
    for (int i = 0; i < 4; i++) {
        __half h0 = __float2half(v[2 * i]);
        __half h1 = __float2half(v[2 * i + 1]);
        __half l0 = __float2half(v[2 * i] - __half2float(h0));
        __half l1 = __float2half(v[2 * i + 1] - __half2float(h1));
        __half2 hh = __halves2half2(h0, h1);
        __half2 ll = __halves2half2(l0, l1);
        ph[i] = *(u32*)&hh; pl[i] = *(u32*)&ll;
    }
    *(uint4*)&dH[(size_t)id * 8] = make_uint4(ph[0], ph[1], ph[2], ph[3]);
    *(uint4*)&dL[(size_t)id * 8] = make_uint4(pl[0], pl[1], pl[2], pl[3]);
}

__global__ void k_xfragX() {
    int id = blockIdx.x * 256 + threadIdx.x;
    if (id >= 16 * 16 * 32) return;
    frag_write(g_XfH, g_XfL, g_X, NA, id);
}
__global__ void k_xfragA() {
    int id = blockIdx.x * 256 + threadIdx.x;
    if (id >= 12 * 16 * 32) return;
    frag_write(g_AfH, g_AfL, g_A, D_, id);
}

// ---------------- k_ista: HMMA fp16-split ISTA ----------------
// SMEM: csH [72][264] half 38016B | csL 38016B | qf 73728B f32  -> 149760B
#define CSH_OFF 0
#define CSL_OFF 38016
#define QF_OFF  76032
#define SM_ISTA 149760

// acc[2][9][4] += frag-GEMM over nks k-steps; B from csH/csL
__device__ __forceinline__ void frag_gemm(float (&acc)[2][9][4],
                                          const __half* __restrict__ fH,
                                          const __half* __restrict__ fL,
                                          int nks, const __half* csH, const __half* csL,
                                          int t0, int lane, int g, int tg) {
    const uint4* FH = (const uint4*)fH;
    const uint4* FL = (const uint4*)fL;
    uint4 ah[2], al[2];
    ah[0] = FH[(0 * 16 + t0) * 32 + lane];
    ah[1] = FH[(0 * 16 + t0 + 1) * 32 + lane];
    al[0] = FL[(0 * 16 + t0) * 32 + lane];
    al[1] = FL[(0 * 16 + t0 + 1) * 32 + lane];
    for (int s = 0; s < nks; s++) {
        uint4 nh[2], nl[2];
        if (s + 1 < nks) {
            nh[0] = FH[((s + 1) * 16 + t0) * 32 + lane];
            nh[1] = FH[((s + 1) * 16 + t0 + 1) * 32 + lane];
            nl[0] = FL[((s + 1) * 16 + t0) * 32 + lane];
            nl[1] = FL[((s + 1) * 16 + t0 + 1) * 32 + lane];
        }
        const __half* bh = csH + g * CSTR + s * 16 + 2 * tg;
        const __half* bl = csL + g * CSTR + s * 16 + 2 * tg;
#pragma unroll
        for (int nt = 0; nt < 9; nt++) {
            u32 b0h = *(const u32*)(bh + nt * 8 * CSTR);
            u32 b1h = *(const u32*)(bh + nt * 8 * CSTR + 8);
            u32 b0l = *(const u32*)(bl + nt * 8 * CSTR);
            u32 b1l = *(const u32*)(bl + nt * 8 * CSTR + 8);
            mma16816(acc[0][nt], (const u32*)&ah[0], b0h, b1h);
            mma16816(acc[1][nt], (const u32*)&ah[1], b0h, b1h);
            mma16816(acc[0][nt], (const u32*)&al[0], b0h, b1h);
            mma16816(acc[1][nt], (const u32*)&al[1], b0h, b1h);
            mma16816(acc[0][nt], (const u32*)&ah[0], b0l, b1l);
            mma16816(acc[1][nt], (const u32*)&ah[1], b0l, b1l);
        }
        ah[0] = nh[0]; ah[1] = nh[1]; al[0] = nl[0]; al[1] = nl[1];
    }
}

__global__ void __launch_bounds__(256, 1) k_ista(const float* __restrict__ y) {
    extern __shared__ char smb[];
    __half* csH = (__half*)(smb + CSH_OFF);
    __half* csL = (__half*)(smb + CSL_OFF);
    float* qf = (float*)(smb + QF_OFF);
    const int tid = threadIdx.x;
    const int w = tid >> 5, lane = tid & 31, g = lane >> 2, tg = lane & 3;
    const int t0 = 2 * w;
    const int n0 = blockIdx.x * T_;
    const float invL = g_params[1], thr = g_params[2];

    // gather centered patches into cs hi/lo ([n][k], k = dim, k<192)
    for (int e = tid; e < 72 * 192; e += 256) {
        int j = e / 192, d = e % 192;
        int n = n0 + j;
        int b = n / 3969, r = n % 3969, pi = r / 63, pj = r % 63;
        int ch = d >> 6, u = (d >> 3) & 7, v = d & 7;
        float pv = y[((b * 3 + ch) * 256 + pi * 4 + u) * 256 + pj * 4 + v] - g_mean[n];
        __half h = __float2half(pv);
        csH[j * CSTR + d] = h;
        csL[j * CSTR + d] = __float2half(pv - __half2float(h));
    }
    __syncthreads();

    float acc[2][9][4];
#pragma unroll
    for (int a = 0; a < 2; a++)
#pragma unroll
        for (int b = 0; b < 9; b++)
#pragma unroll
            for (int cdx = 0; cdx < 4; cdx++) acc[a][b][cdx] = 0.f;

    // ---- q = A @ p^T : 12 k-steps ----
    frag_gemm(acc, g_AfH, g_AfL, 12, csH, csL, t0, lane, g, tg);
    __syncthreads();   // all B reads done before cs overwritten with c1

#pragma unroll
    for (int t = 0; t < 2; t++) {
        int kb = (t0 + t) * 16;
#pragma unroll
        for (int nt = 0; nt < 9; nt++) {
            float* qp = &qf[(((t0 + t) * 9 + nt) * 32 + lane) * 4];
            *(float4*)qp = make_float4(acc[t][nt][0], acc[t][nt][1], acc[t][nt][2], acc[t][nt][3]);
            int k0 = kb + g, k1 = kb + g + 8;
            int nA = nt * 8 + 2 * tg, nB2 = nA + 1;
            float cv;
            cv = softthr(acc[t][nt][0] * invL, thr);
            { __half h = __float2half(cv); csH[nA * CSTR + k0] = h; csL[nA * CSTR + k0] = __float2half(cv - __half2float(h)); }
            cv = softthr(acc[t][nt][1] * invL, thr);
            { __half h = __float2half(cv); csH[nB2 * CSTR + k0] = h; csL[nB2 * CSTR + k0] = __float2half(cv - __half2float(h)); }
            cv = softthr(acc[t][nt][2] * invL, thr);
            { __half h = __float2half(cv); csH[nA * CSTR + k1] = h; csL[nA * CSTR + k1] = __float2half(cv - __half2float(h)); }
            cv = softthr(acc[t][nt][3] * invL, thr);
            { __half h = __float2half(cv); csH[nB2 * CSTR + k1] = h; csL[nB2 * CSTR + k1] = __float2half(cv - __half2float(h)); }
        }
    }
    __syncthreads();

    // ---- 24 ISTA iterations ----
    for (int it = 0; it < 24; it++) {
#pragma unroll
        for (int a = 0; a < 2; a++)
#pragma unroll
            for (int b = 0; b < 9; b++)
#pragma unroll
                for (int cdx = 0; cdx < 4; cdx++) acc[a][b][cdx] = 0.f;
        frag_gemm(acc, g_XfH, g_XfL, 16, csH, csL, t0, lane, g, tg);
        __syncthreads();   // all warps done reading cs
#pragma unroll
        for (int t = 0; t < 2; t++) {
            int kb = (t0 + t) * 16;
#pragma unroll
            for (int nt = 0; nt < 9; nt++) {
                float4 q = *(const float4*)&qf[(((t0 + t) * 9 + nt) * 32 + lane) * 4];
                int k0 = kb + g, k1 = kb + g + 8;
                int nA = nt * 8 + 2 * tg, nB2 = nA + 1;
                float qv[4] = {q.x, q.y, q.z, q.w};
                int kk[4] = {k0, k0, k1, k1};
                int nn[4] = {nA, nB2, nA, nB2};
#pragma unroll
                for (int e = 0; e < 4; e++) {
                    int idx = nn[e] * CSTR + kk[e];
                    float cold = __half2float(csH[idx]) + __half2float(csL[idx]);
                    float cn = softthr(cold - (acc[t][nt][e] - qv[e]) * invL, thr);
                    __half h = __float2half(cn);
                    csH[idx] = h;
                    csL[idx] = __float2half(cn - __half2float(h));
                }
            }
        }
        __syncthreads();
    }

    // ---- write final c to global [n][a] ----
    for (int e = tid; e < 72 * 256; e += 256) {
        int n = e >> 8, a = e & 255;
        g_c[(size_t)(n0 + n) * NA + a] =
            __half2float(csH[n * CSTR + a]) + __half2float(csL[n * CSTR + a]);
    }
}

// ---------------- k_rec: rec = c^T A + mean (fp32 FFMA2, proven structure) ----------------
#define RTHR 576
#define CS2_OFF 0
#define XSH_OFF (72 * 256)
#define RMS_OFF (XSH_OFF + 2 * 3072)
#define SM_REC ((RMS_OFF + T_) * 4)

__global__ void __launch_bounds__(RTHR, 1) k_rec() {
    extern __shared__ float smf[];
    float* cs2 = smf + CS2_OFF;
    float* Xsh = smf + XSH_OFF;
    float* msh = smf + RMS_OFF;
    const int tid = threadIdx.x;
    const int n0 = blockIdx.x * T_;
    for (int i = tid; i < 72 * 256; i += RTHR)
        cs2[i] = g_c[(size_t)(n0 + (i >> 8)) * NA + (i & 255)];
    if (tid < T_) msh[tid] = g_mean[n0 + tid];

    const int dg = tid & 31, jg = tid >> 5;
    const int d0 = dg * 6, j0e = jg * 4;
    ull racc[4][3];
#pragma unroll
    for (int a = 0; a < 4; a++)
#pragma unroll
        for (int b = 0; b < 3; b++) racc[a][b] = 0ull;

    for (int i = tid; i < 768; i += RTHR) {
        int aa = i / 48, dd = (i % 48) * 4;
        *(float4*)&Xsh[aa * 192 + dd] = *(const float4*)&g_A[aa * 192 + dd];
    }
    __syncthreads();
    for (int s = 0; s < 16; s++) {
        float4 pf0, pf1;
        bool have1 = false;
        if (s + 1 < 16) {
            const float* src = g_A + (s + 1) * 3072;
            int aa = tid / 48, dd = (tid % 48) * 4;
            pf0 = *(const float4*)&src[aa * 192 + dd];
            if (tid + RTHR < 768) {
                int i1 = tid + RTHR; aa = i1 / 48; dd = (i1 % 48) * 4;
                pf1 = *(const float4*)&src[aa * 192 + dd];
                have1 = true;
            }
        }
        const float* Ab = Xsh + (s & 1) * 3072;
#pragma unroll
        for (int kk = 0; kk < 16; kk++) {
            int a = s * 16 + kk;
            float c0v = cs2[(j0e + 0) * 256 + a];
            float c1v = cs2[(j0e + 1) * 256 + a];
            float c2v = cs2[(j0e + 2) * 256 + a];
            float c3v = cs2[(j0e + 3) * 256 + a];
            ull ap0 = *(const ull*)&Ab[kk * 192 + d0];
            ull ap1 = *(const ull*)&Ab[kk * 192 + d0 + 2];
            ull ap2 = *(const ull*)&Ab[kk * 192 + d0 + 4];
            ull c0 = pk2(c0v, c0v), c1 = pk2(c1v, c1v);
            ull c2 = pk2(c2v, c2v), c3 = pk2(c3v, c3v);
            racc[0][0] = f2fma(ap0, c0, racc[0][0]); racc[0][1] = f2fma(ap1, c0, racc[0][1]); racc[0][2] = f2fma(ap2, c0, racc[0][2]);
            racc[1][0] = f2fma(ap0, c1, racc[1][0]); racc[1][1] = f2fma(ap1, c1, racc[1][1]); racc[1][2] = f2fma(ap2, c1, racc[1][2]);
            racc[2][0] = f2fma(ap0, c2, racc[2][0]); racc[2][1] = f2fma(ap1, c2, racc[2][1]); racc[2][2] = f2fma(ap2, c2, racc[2][2]);
            racc[3][0] = f2fma(ap0, c3, racc[3][0]); racc[3][1] = f2fma(ap1, c3, racc[3][1]); racc[3][2] = f2fma(ap2, c3, racc[3][2]);
        }
        __syncthreads();
        if (s + 1 < 16) {
            float* dst = Xsh + ((s + 1) & 1) * 3072;
            int aa = tid / 48, dd = (tid % 48) * 4;
            *(float4*)&dst[aa * 192 + dd] = pf0;
            if (have1) {
                int i1 = tid + RTHR; aa = i1 / 48; dd = (i1 % 48) * 4;
                *(float4*)&dst[aa * 192 + dd] = pf1;
            }
            __syncthreads();
        }
    }
#pragma unroll
    for (int jj = 0; jj < 4; jj++) {
        int n = n0 + j0e + jj;
        float m = msh[j0e + jj];
        float* o = g_rec + (size_t)n * D_ + d0;
#pragma unroll
        for (int dp = 0; dp < 3; dp++) {
            float lo, hi; up2(racc[jj][dp], lo, hi);
            o[2 * dp] = lo + m;
            o[2 * dp + 1] = hi + m;
        }
    }
}

// ---------------- k_out ----------------
__global__ void k_out(float* __restrict__ out) {
    int idx = blockIdx.x * 256 + threadIdx.x;
    if (idx >= 8 * 3 * 256 * 256) return;
    int w = idx & 255, h = (idx >> 8) & 255;
    int ch = (idx >> 16) % 3, b = (idx >> 16) / 3;
    int ihi = h >> 2; if (ihi > 62) ihi = 62;
    int ilo = (h >= 7) ? ((h - 4) >> 2) : 0;
    int jhi = w >> 2; if (jhi > 62) jhi = 62;
    int jlo = (w >= 7) ? ((w - 4) >> 2) : 0;
    float s = 0.f;
    int cnt = 0;
    for (int i = ilo; i <= ihi; i++) {
        int u = h - 4 * i;
        for (int j = jlo; j <= jhi; j++) {
            int v = w - 4 * j;
            int n = b * 3969 + i * 63 + j;
            s += g_rec[(size_t)n * D_ + ch * 64 + u * 8 + v];
            cnt++;
        }
    }
    out[idx] = s / (float)cnt;
}

// ---------------- host launcher ----------------
extern "C" void kernel_launch(void* const* d_in, const int* in_sizes, int n_in,
                              void* d_out, int out_size) {
    const float* y = (const float*)d_in[0];
    const float* atoms = (const float*)d_in[1];
    if (n_in >= 2 && in_sizes[0] < in_sizes[1]) {
        y = (const float*)d_in[1];
        atoms = (const float*)d_in[0];
    }
    float* out = (float*)d_out;

    k_reset<<<1, 32>>>();                          // 0
    k_chain<<<NB, 256>>>(atoms);                   // 1
    k_mean<<<NP / 8, 256>>>(y);                    // 2
    k_xfragX<<<32, 256>>>();                       // 3
    k_xfragA<<<24, 256>>>();                       // 4

    cudaFuncSetAttribute(k_ista, cudaFuncAttributeMaxDynamicSharedMemorySize, SM_ISTA);
    k_ista<<<NCTA, 256, SM_ISTA>>>(y);             // 5 (profiled by -s 5)

    cudaFuncSetAttribute(k_rec, cudaFuncAttributeMaxDynamicSharedMemorySize, SM_REC);
    k_rec<<<NCTA, RTHR, SM_REC>>>();               // 6

    k_out<<<(8 * 3 * 256 * 256 + 255) / 256, 256>>>(out);  // 7
}

// round 12
// speedup vs baseline: 3.8065x; 1.0882x over previous
#include <cuda_runtime.h>
#include <cuda_fp16.h>
#include <math.h>

#define NP   31752
#define D_   192
#define NA   256
#define LMB  0.1f
#define NSQ  10
#define T_   72
#define NCTA 441
#define NB   64
#define CSTR 264                 // cs row stride in halfs

typedef unsigned long long ull;
typedef unsigned int u32;

// ---------------- static device scratch ----------------
__device__ float  g_A[NA * D_];
__device__ float  g_At[D_ * NA];
__device__ float  g_X[NA * NA];
__device__ float  g_Ma[NA * NA];
__device__ float  g_Mb[NA * NA];
__device__ __half g_XfH[16 * 16 * 32 * 8];    // X frags [s16][t16][lane][8]
__device__ __half g_XfL[16 * 16 * 32 * 8];
__device__ __half g_AfH[12 * 16 * 32 * 8];    // dict frags (q-phase) [s12][t16]
__device__ __half g_AfL[12 * 16 * 32 * 8];
__device__ __half g_AtfH[16 * 12 * 32 * 8];   // dict-T frags (rec) [s16][t12]
__device__ __half g_AtfL[16 * 12 * 32 * 8];
__device__ float  g_fs[16];
__device__ float  g_params[4];
__device__ float  g_rec[(size_t)NP * D_];
__device__ unsigned g_arrive = 0;

// ---------------- helpers ----------------
__device__ __forceinline__ float softthr(float v, float thr) {
    float a = fabsf(v) - thr;
    return a > 0.f ? copysignf(a, v) : 0.f;
}
__device__ __forceinline__ void mma16816(float* d, const u32* a, u32 b0, u32 b1) {
    asm volatile(
        "mma.sync.aligned.m16n8k16.row.col.f32.f16.f16.f32 "
        "{%0,%1,%2,%3}, {%4,%5,%6,%7}, {%8,%9}, {%0,%1,%2,%3};"
        : "+f"(d[0]), "+f"(d[1]), "+f"(d[2]), "+f"(d[3])
        : "r"(a[0]), "r"(a[1]), "r"(a[2]), "r"(a[3]), "r"(b0), "r"(b1));
}

// ---------------- k_reset + grid barrier ----------------
__global__ void k_reset() { if (threadIdx.x == 0) g_arrive = 0; }

__device__ __forceinline__ void gsync(unsigned target) {
    __threadfence();
    __syncthreads();
    if (threadIdx.x == 0) {
        atomicAdd(&g_arrive, 1u);
        while (*((volatile unsigned*)&g_arrive) < target) { }
        __threadfence();
    }
    __syncthreads();
}

// ---------------- k_chain (proven): normalize + Gram + spectral norm ----------------
__global__ void __launch_bounds__(256, 1) k_chain(const float* __restrict__ atoms) {
    __shared__ float AshT[NA * 4];
    __shared__ float red[256];
    const int tid = threadIdx.x;
    const int cta = blockIdx.x;
    const int r0 = cta * 4;
    unsigned bar = 0;

    if (cta == 0 && tid < 16) g_fs[tid] = 0.f;
    {
        int r = tid >> 6, l = tid & 63;
        int row = r0 + r;
        float v0 = atoms[row * D_ + l];
        float v1 = atoms[row * D_ + l + 64];
        float v2 = atoms[row * D_ + l + 128];
        red[tid] = v0 * v0 + v1 * v1 + v2 * v2;
        __syncthreads();
        for (int o = 32; o > 0; o >>= 1) {
            if (l < o) red[tid] += red[tid + o];
            __syncthreads();
        }
        float inv = 1.0f / sqrtf(red[r * 64]);
        float a0 = v0 * inv, a1 = v1 * inv, a2 = v2 * inv;
        g_A[row * D_ + l]       = a0;  g_At[l * NA + row]         = a0;
        g_A[row * D_ + l + 64]  = a1;  g_At[(l + 64) * NA + row]  = a1;
        g_A[row * D_ + l + 128] = a2;  g_At[(l + 128) * NA + row] = a2;
    }
    gsync(++bar * NB);

    {
        for (int i = tid; i < 4 * D_; i += 256) {
            int r = i / D_, k = i % D_;
            AshT[k * 4 + r] = g_A[(r0 + r) * D_ + k];
        }
        __syncthreads();
        int c = tid;
        float acc0 = 0.f, acc1 = 0.f, acc2 = 0.f, acc3 = 0.f;
        for (int k = 0; k < D_; k++) {
            float b = __ldcg(&g_At[k * NA + c]);
            float4 a4 = *(const float4*)&AshT[k * 4];
            acc0 += a4.x * b; acc1 += a4.y * b; acc2 += a4.z * b; acc3 += a4.w * b;
        }
        g_X[(r0 + 0) * NA + c] = acc0;
        g_X[(r0 + 1) * NA + c] = acc1;
        g_X[(r0 + 2) * NA + c] = acc2;
        g_X[(r0 + 3) * NA + c] = acc3;
        float fsum = acc0 * acc0 + acc1 * acc1 + acc2 * acc2 + acc3 * acc3;
#pragma unroll
        for (int o = 16; o > 0; o >>= 1) fsum += __shfl_xor_sync(0xffffffffu, fsum, o);
        if ((tid & 31) == 0) atomicAdd(&g_fs[1], fsum);
        __syncthreads();
    }
    gsync(++bar * NB);

    const float* In = g_X;
    float* Out = g_Ma;
    for (int j = 1; j <= NSQ; j++) {
        float scale = 1.0f / __ldcg(&g_fs[j]);
        for (int i = tid; i < 1024; i += 256) {
            int r = i >> 8, k = i & 255;
            AshT[k * 4 + r] = __ldcg(&In[(r0 + r) * NA + k]);
        }
        __syncthreads();
        int c = tid;
        float acc0 = 0.f, acc1 = 0.f, acc2 = 0.f, acc3 = 0.f;
        for (int k = 0; k < NA; k++) {
            float b = __ldcg(&In[k * NA + c]);
            float4 a4 = *(const float4*)&AshT[k * 4];
            acc0 += a4.x * b; acc1 += a4.y * b; acc2 += a4.z * b; acc3 += a4.w * b;
        }
        acc0 *= scale; acc1 *= scale; acc2 *= scale; acc3 *= scale;
        Out[(r0 + 0) * NA + c] = acc0;
        Out[(r0 + 1) * NA + c] = acc1;
        Out[(r0 + 2) * NA + c] = acc2;
        Out[(r0 + 3) * NA + c] = acc3;
        float fsum = acc0 * acc0 + acc1 * acc1 + acc2 * acc2 + acc3 * acc3;
#pragma unroll
        for (int o = 16; o > 0; o >>= 1) fsum += __shfl_xor_sync(0xffffffffu, fsum, o);
        if ((tid & 31) == 0) atomicAdd(&g_fs[j + 1], fsum);
        const float* nIn = Out;
        Out = (Out == g_Ma) ? g_Mb : g_Ma;
        In = nIn;
        gsync(++bar * NB);
    }

    if (cta == 0) {
        red[tid] = __ldcg(&In[tid * NA + tid]);
        __syncthreads();
        for (int o = 128; o > 0; o >>= 1) {
            if (tid < o) red[tid] += red[tid + o];
            __syncthreads();
        }
        if (tid == 0) {
            double lg = log((double)red[0]);
            for (int j = 1; j <= NSQ; j++)
                lg += (double)(1 << (NSQ - j)) * log((double)__ldcg(&g_fs[j]));
            double L = exp(lg / (double)(1 << NSQ));
            g_params[0] = (float)L;
            g_params[1] = (float)(1.0 / L);
            g_params[2] = (float)((double)LMB / L);
        }
    }
}

// ---------------- fragment pre-swizzle ----------------
// fragment for A-operand tile (m-tile t, k-chunk s): lane holds 8 halfs
__device__ __forceinline__ void frag_core(__half* dH, __half* dL,
                                          const float* __restrict__ src, int stride,
                                          int s, int t, int lane, size_t sidx) {
    int g = lane >> 2, tg = lane & 3;
    int r = t * 16 + g, k = s * 16 + 2 * tg;
    float v[8];
    v[0] = src[r * stride + k];           v[1] = src[r * stride + k + 1];
    v[2] = src[(r + 8) * stride + k];     v[3] = src[(r + 8) * stride + k + 1];
    v[4] = src[r * stride + k + 8];       v[5] = src[r * stride + k + 9];
    v[6] = src[(r + 8) * stride + k + 8]; v[7] = src[(r + 8) * stride + k + 9];
    u32 ph[4], pl[4];
#pragma unroll
    for (int i = 0; i < 4; i++) {
        __half h0 = __float2half(v[2 * i]);
        __half h1 = __float2half(v[2 * i + 1]);
        __half l0 = __float2half(v[2 * i] - __half2float(h0));
        __half l1 = __float2half(v[2 * i + 1] - __half2float(h1));
        __half2 hh = __halves2half2(h0, h1);
        __half2 ll = __halves2half2(l0, l1);
        ph[i] = *(u32*)&hh; pl[i] = *(u32*)&ll;
    }
    *(uint4*)&dH[sidx * 8] = make_uint4(ph[0], ph[1], ph[2], ph[3]);
    *(uint4*)&dL[sidx * 8] = make_uint4(pl[0], pl[1], pl[2], pl[3]);
}

__global__ void k_xfragX() {     // X: 16 m-tiles x 16 k-chunks, storage (s*16+t)
    int id = blockIdx.x * 256 + threadIdx.x;
    if (id >= 16 * 16 * 32) return;
    int lane = id & 31, t = (id >> 5) & 15, s = id >> 9;
    frag_core(g_XfH, g_XfL, g_X, NA, s, t, lane, (size_t)(s * 16 + t) * 32 + lane);
}
__global__ void k_xfragA() {     // A (q-phase): 16 m-tiles x 12 k-chunks, storage (s*16+t)
    int id = blockIdx.x * 256 + threadIdx.x;
    if (id >= 12 * 16 * 32) return;
    int lane = id & 31, t = (id >> 5) & 15, s = id >> 9;
    frag_core(g_AfH, g_AfL, g_A, D_, s, t, lane, (size_t)(s * 16 + t) * 32 + lane);
}
__global__ void k_xfragAt() {    // At (rec): 12 m-tiles(d) x 16 k-chunks(atoms), storage (s*12+t)
    int id = blockIdx.x * 256 + threadIdx.x;
    if (id >= 16 * 12 * 32) return;
    int lane = id & 31, rest = id >> 5;
    int t = rest % 12, s = rest / 12;
    frag_core(g_AtfH, g_AtfL, g_At, NA, s, t, lane, (size_t)(s * 12 + t) * 32 + lane);
}

// ---------------- k_ista: HMMA split ISTA + fused mean + fused rec ----------------
// SMEM: csH 38016 | csL 38016 | qf 73728 | msh 288  -> 150048 bytes
#define CSH_OFF 0
#define CSL_OFF 38016
#define QF_OFF  76032
#define MSH_OFF 149760
#define SM_ISTA 150048

__device__ __forceinline__ void frag_gemm(float (&acc)[2][9][4],
                                          const __half* __restrict__ fH,
                                          const __half* __restrict__ fL,
                                          int nks, const __half* csH, const __half* csL,
                                          int t0, int lane, int g, int tg) {
    const uint4* FH = (const uint4*)fH;
    const uint4* FL = (const uint4*)fL;
    uint4 ah[2], al[2];
    ah[0] = FH[(0 * 16 + t0) * 32 + lane];
    ah[1] = FH[(0 * 16 + t0 + 1) * 32 + lane];
    al[0] = FL[(0 * 16 + t0) * 32 + lane];
    al[1] = FL[(0 * 16 + t0 + 1) * 32 + lane];
    for (int s = 0; s < nks; s++) {
        uint4 nh[2], nl[2];
        if (s + 1 < nks) {
            nh[0] = FH[((s + 1) * 16 + t0) * 32 + lane];
            nh[1] = FH[((s + 1) * 16 + t0 + 1) * 32 + lane];
            nl[0] = FL[((s + 1) * 16 + t0) * 32 + lane];
            nl[1] = FL[((s + 1) * 16 + t0 + 1) * 32 + lane];
        }
        const __half* bh = csH + g * CSTR + s * 16 + 2 * tg;
        const __half* bl = csL + g * CSTR + s * 16 + 2 * tg;
#pragma unroll
        for (int nt = 0; nt < 9; nt++) {
            u32 b0h = *(const u32*)(bh + nt * 8 * CSTR);
            u32 b1h = *(const u32*)(bh + nt * 8 * CSTR + 8);
            u32 b0l = *(const u32*)(bl + nt * 8 * CSTR);
            u32 b1l = *(const u32*)(bl + nt * 8 * CSTR + 8);
            mma16816(acc[0][nt], (const u32*)&ah[0], b0h, b1h);
            mma16816(acc[1][nt], (const u32*)&ah[1], b0h, b1h);
            mma16816(acc[0][nt], (const u32*)&al[0], b0h, b1h);
            mma16816(acc[1][nt], (const u32*)&al[1], b0h, b1h);
            mma16816(acc[0][nt], (const u32*)&ah[0], b0l, b1l);
            mma16816(acc[1][nt], (const u32*)&ah[1], b0l, b1l);
        }
        ah[0] = nh[0]; ah[1] = nh[1]; al[0] = nl[0]; al[1] = nl[1];
    }
}

__global__ void __launch_bounds__(256, 1) k_ista(const float* __restrict__ y) {
    extern __shared__ char smb[];
    __half* csH = (__half*)(smb + CSH_OFF);
    __half* csL = (__half*)(smb + CSL_OFF);
    float* qf = (float*)(smb + QF_OFF);
    float* msh = (float*)(smb + MSH_OFF);
    const int tid = threadIdx.x;
    const int w = tid >> 5, lane = tid & 31, g = lane >> 2, tg = lane & 3;
    const int t0 = 2 * w;
    const int n0 = blockIdx.x * T_;
    const float invL = g_params[1], thr = g_params[2];

    // ---- fused per-patch mean: warp w handles patches w*9 .. w*9+8 ----
    for (int i = 0; i < 9; i++) {
        int j = w * 9 + i;
        int n = n0 + j;
        int b = n / 3969, r = n % 3969, pi = r / 63, pj = r % 63;
        float s = 0.f;
#pragma unroll
        for (int dd = 0; dd < 6; dd++) {
            int d = lane * 6 + dd;
            int ch = d >> 6, u = (d >> 3) & 7, v = d & 7;
            s += y[((b * 3 + ch) * 256 + pi * 4 + u) * 256 + pj * 4 + v];
        }
#pragma unroll
        for (int o = 16; o > 0; o >>= 1) s += __shfl_xor_sync(0xffffffffu, s, o);
        if (lane == 0) msh[j] = s * (1.f / 192.f);
    }
    __syncthreads();

    // ---- gather centered patches into cs hi/lo ([n][k], k = dim < 192) ----
    for (int e = tid; e < 72 * 192; e += 256) {
        int j = e / 192, d = e % 192;
        int n = n0 + j;
        int b = n / 3969, r = n % 3969, pi = r / 63, pj = r % 63;
        int ch = d >> 6, u = (d >> 3) & 7, v = d & 7;
        float pv = y[((b * 3 + ch) * 256 + pi * 4 + u) * 256 + pj * 4 + v] - msh[j];
        __half h = __float2half(pv);
        csH[j * CSTR + d] = h;
        csL[j * CSTR + d] = __float2half(pv - __half2float(h));
    }
    __syncthreads();

    float acc[2][9][4];
    float c_reg[2][9][4];
#pragma unroll
    for (int a = 0; a < 2; a++)
#pragma unroll
        for (int b = 0; b < 9; b++)
#pragma unroll
            for (int e = 0; e < 4; e++) acc[a][b][e] = 0.f;

    // ---- q = A @ p^T : 12 k-chunks ----
    frag_gemm(acc, g_AfH, g_AfL, 12, csH, csL, t0, lane, g, tg);
    __syncthreads();   // all B reads done before cs overwritten

#pragma unroll
    for (int t = 0; t < 2; t++) {
        int kb = (t0 + t) * 16;
#pragma unroll
        for (int nt = 0; nt < 9; nt++) {
            *(float4*)&qf[(((t0 + t) * 9 + nt) * 32 + lane) * 4] =
                make_float4(acc[t][nt][0], acc[t][nt][1], acc[t][nt][2], acc[t][nt][3]);
#pragma unroll
            for (int e = 0; e < 4; e++) {
                float cv = softthr(acc[t][nt][e] * invL, thr);
                c_reg[t][nt][e] = cv;
                int n = nt * 8 + 2 * tg + (e & 1);
                int m = kb + g + 8 * (e >> 1);
                __half h = __float2half(cv);
                csH[n * CSTR + m] = h;
                csL[n * CSTR + m] = __float2half(cv - __half2float(h));
            }
        }
    }
    __syncthreads();

    // ---- 24 remaining ISTA iterations ----
    for (int it = 0; it < 24; it++) {
#pragma unroll
        for (int a = 0; a < 2; a++)
#pragma unroll
            for (int b = 0; b < 9; b++)
#pragma unroll
                for (int e = 0; e < 4; e++) acc[a][b][e] = 0.f;
        frag_gemm(acc, g_XfH, g_XfL, 16, csH, csL, t0, lane, g, tg);
        __syncthreads();
#pragma unroll
        for (int t = 0; t < 2; t++) {
            int kb = (t0 + t) * 16;
#pragma unroll
            for (int nt = 0; nt < 9; nt++) {
                float4 q = *(const float4*)&qf[(((t0 + t) * 9 + nt) * 32 + lane) * 4];
                float qv[4] = {q.x, q.y, q.z, q.w};
#pragma unroll
                for (int e = 0; e < 4; e++) {
                    float cn = softthr(c_reg[t][nt][e] - (acc[t][nt][e] - qv[e]) * invL, thr);
                    c_reg[t][nt][e] = cn;
                    int n = nt * 8 + 2 * tg + (e & 1);
                    int m = kb + g + 8 * (e >> 1);
                    __half h = __float2half(cn);
                    csH[n * CSTR + m] = h;
                    csL[n * CSTR + m] = __float2half(cn - __half2float(h));
                }
            }
        }
        __syncthreads();
    }

    // ---- fused rec = c^T A + mean : contraction over atoms (16 k-chunks) ----
    {
        const uint4* FH = (const uint4*)g_AtfH;
        const uint4* FL = (const uint4*)g_AtfL;
        float r0a[9][4], r1a[9][4];
#pragma unroll
        for (int b = 0; b < 9; b++)
#pragma unroll
            for (int e = 0; e < 4; e++) { r0a[b][e] = 0.f; r1a[b][e] = 0.f; }
        const int tt0 = w;            // tiles 0..7
        const int tt1 = 8 + w;        // tiles 8..11 (warps 0..3)
        const bool has2 = (w < 4);
        for (int s = 0; s < 16; s++) {
            uint4 ah0 = FH[(s * 12 + tt0) * 32 + lane];
            uint4 al0 = FL[(s * 12 + tt0) * 32 + lane];
            uint4 ah1, al1;
            if (has2) {
                ah1 = FH[(s * 12 + tt1) * 32 + lane];
                al1 = FL[(s * 12 + tt1) * 32 + lane];
            }
            const __half* bh = csH + g * CSTR + s * 16 + 2 * tg;
            const __half* bl = csL + g * CSTR + s * 16 + 2 * tg;
#pragma unroll
            for (int nt = 0; nt < 9; nt++) {
                u32 b0h = *(const u32*)(bh + nt * 8 * CSTR);
                u32 b1h = *(const u32*)(bh + nt * 8 * CSTR + 8);
                u32 b0l = *(const u32*)(bl + nt * 8 * CSTR);
                u32 b1l = *(const u32*)(bl + nt * 8 * CSTR + 8);
                mma16816(r0a[nt], (const u32*)&ah0, b0h, b1h);
                mma16816(r0a[nt], (const u32*)&al0, b0h, b1h);
                mma16816(r0a[nt], (const u32*)&ah0, b0l, b1l);
                if (has2) {
                    mma16816(r1a[nt], (const u32*)&ah1, b0h, b1h);
                    mma16816(r1a[nt], (const u32*)&al1, b0h, b1h);
                    mma16816(r1a[nt], (const u32*)&ah1, b0l, b1l);
                }
            }
        }
#pragma unroll
        for (int nt = 0; nt < 9; nt++)
#pragma unroll
            for (int e = 0; e < 4; e++) {
                int n = nt * 8 + 2 * tg + (e & 1);
                int d = tt0 * 16 + g + 8 * (e >> 1);
                float m = msh[n];
                g_rec[(size_t)(n0 + n) * D_ + d] = r0a[nt][e] + m;
                if (has2) {
                    int d1 = tt1 * 16 + g + 8 * (e >> 1);
                    g_rec[(size_t)(n0 + n) * D_ + d1] = r1a[nt][e] + m;
                }
            }
    }
}

// ---------------- k_out ----------------
__global__ void k_out(float* __restrict__ out) {
    int idx = blockIdx.x * 256 + threadIdx.x;
    if (idx >= 8 * 3 * 256 * 256) return;
    int w = idx & 255, h = (idx >> 8) & 255;
    int ch = (idx >> 16) % 3, b = (idx >> 16) / 3;
    int ihi = h >> 2; if (ihi > 62) ihi = 62;
    int ilo = (h >= 7) ? ((h - 4) >> 2) : 0;
    int jhi = w >> 2; if (jhi > 62) jhi = 62;
    int jlo = (w >= 7) ? ((w - 4) >> 2) : 0;
    float s = 0.f;
    int cnt = 0;
    for (int i = ilo; i <= ihi; i++) {
        int u = h - 4 * i;
        for (int j = jlo; j <= jhi; j++) {
            int v = w - 4 * j;
            int n = b * 3969 + i * 63 + j;
            s += g_rec[(size_t)n * D_ + ch * 64 + u * 8 + v];
            cnt++;
        }
    }
    out[idx] = s / (float)cnt;
}

// ---------------- host launcher ----------------
extern "C" void kernel_launch(void* const* d_in, const int* in_sizes, int n_in,
                              void* d_out, int out_size) {
    const float* y = (const float*)d_in[0];
    const float* atoms = (const float*)d_in[1];
    if (n_in >= 2 && in_sizes[0] < in_sizes[1]) {
        y = (const float*)d_in[1];
        atoms = (const float*)d_in[0];
    }
    float* out = (float*)d_out;

    k_reset<<<1, 32>>>();                          // 0
    k_chain<<<NB, 256>>>(atoms);                   // 1
    k_xfragX<<<32, 256>>>();                       // 2
    k_xfragA<<<24, 256>>>();                       // 3
    k_xfragAt<<<24, 256>>>();                      // 4

    cudaFuncSetAttribute(k_ista, cudaFuncAttributeMaxDynamicSharedMemorySize, SM_ISTA);
    k_ista<<<NCTA, 256, SM_ISTA>>>(y);             // 5 (profiled by -s 5)

    k_out<<<(8 * 3 * 256 * 256 + 255) / 256, 256>>>(out);  // 6
}